// round 6
// baseline (speedup 1.0000x reference)
#include <cuda_runtime.h>
#include <cuda_fp16.h>
#include <cstdint>

#define NN 50000
#define F1 256
#define F2 128
#define EMAX 2000000
#define SCAN_B 1024
#define NBLK ((NN + SCAN_B - 1) / SCAN_B)   // 49

// -------- scratch (static device globals; no allocation) --------
__device__ int g_deg[NN];
__device__ int g_off[NN + 1];
__device__ int g_cur[NN];
__device__ int g_bsum[NBLK];
__device__ int g_srcs[EMAX];
__device__ __align__(16) float  g_dinv[NN];
__device__ __align__(16) __half g_hh1[(size_t)NN * F1];   // fp16 (x@W1)*dinv
__device__ __align__(16) float  g_h1[(size_t)NN * F1];    // relu'd layer-1 out (fp32)
__device__ __align__(16) __half g_hh2[(size_t)NN * F2];   // fp16 (h1@W2)*dinv
__device__ int g_is64;

// -------- edge dtype detection (int64 vs int32) --------
__global__ void k_detect(const int* __restrict__ w, int nwords) {
    __shared__ int ok;
    if (threadIdx.x == 0) ok = 1;
    __syncthreads();
    for (int i = threadIdx.x; i < nwords / 2; i += blockDim.x)
        if (w[2 * i + 1] != 0) ok = 0;   // benign race
    __syncthreads();
    if (threadIdx.x == 0) g_is64 = ok;
}
__device__ __forceinline__ int edge_at(const void* p, int i, int is64) {
    if (is64) return (int)((const long long*)p)[i];
    return ((const int*)p)[i];
}

__global__ void k_zeroint(int* __restrict__ p, int n) {
    int i = blockIdx.x * blockDim.x + threadIdx.x;
    if (i < n) p[i] = 0;
}
__global__ void k_edgedeg(const void* __restrict__ ei, int* __restrict__ deg, int E) {
    int i = blockIdx.x * blockDim.x + threadIdx.x;
    if (i >= E) return;
    int d = edge_at(ei, E + i, g_is64);
    atomicAdd(deg + d, 1);
}

// -------- 3-phase parallel exclusive scan --------
__global__ __launch_bounds__(SCAN_B) void k_scan1(
    const int* __restrict__ deg, int* __restrict__ off, int* __restrict__ bsum)
{
    __shared__ int sh[SCAN_B];
    int t = threadIdx.x;
    int idx = blockIdx.x * SCAN_B + t;
    int v = (idx < NN) ? deg[idx] : 0;
    sh[t] = v;
    __syncthreads();
#pragma unroll
    for (int d = 1; d < SCAN_B; d <<= 1) {
        int u = 0;
        if (t >= d) u = sh[t - d];
        __syncthreads();
        if (t >= d) sh[t] += u;
        __syncthreads();
    }
    if (idx < NN) off[idx] = sh[t] - v;
    if (t == SCAN_B - 1) bsum[blockIdx.x] = sh[t];
}
__global__ void k_scan2(int* __restrict__ bsum, int* __restrict__ off_last) {
    __shared__ int sh[64];
    int t = threadIdx.x;
    int v = (t < NBLK) ? bsum[t] : 0;
    sh[t] = v;
    __syncthreads();
#pragma unroll
    for (int d = 1; d < 64; d <<= 1) {
        int u = 0;
        if (t >= d) u = sh[t - d];
        __syncthreads();
        if (t >= d) sh[t] += u;
        __syncthreads();
    }
    if (t < NBLK) bsum[t] = sh[t] - v;
    if (t == 63) *off_last = sh[63];
}
__global__ void k_scan3(int* __restrict__ off, int* __restrict__ cur,
                        const int* __restrict__ bsum, const int* __restrict__ deg,
                        float* __restrict__ dinv)
{
    int idx = blockIdx.x * SCAN_B + threadIdx.x;
    if (idx >= NN) return;
    int o = off[idx] + bsum[blockIdx.x];
    off[idx] = o;
    cur[idx] = o;
    dinv[idx] = rsqrtf((float)deg[idx] + 1.0f);
}

__global__ void k_bucket(const void* __restrict__ ei, int* __restrict__ cur,
                         int* __restrict__ srcs, int E) {
    int i = blockIdx.x * blockDim.x + threadIdx.x;
    if (i >= E) return;
    int is64 = g_is64;
    int s = edge_at(ei, i, is64);
    int d = edge_at(ei, E + i, is64);
    int p = atomicAdd(cur + d, 1);
    srcs[p] = s;
}

// -------- split helper --------
__device__ __forceinline__ void split_hl(float v, __half& h, __half& l) {
    h = __float2half_rn(v);
    l = __float2half_rn(v - __half2float(h));
}

#define MMA16816(d, a0, a1, a2, a3, b0, b1)                                   \
    asm volatile(                                                             \
        "mma.sync.aligned.m16n8k16.row.col.f32.f16.f16.f32 "                  \
        "{%0,%1,%2,%3}, {%4,%5,%6,%7}, {%8,%9}, {%0,%1,%2,%3};"               \
        : "+f"((d)[0]), "+f"((d)[1]), "+f"((d)[2]), "+f"((d)[3])              \
        : "r"(a0), "r"(a1), "r"(a2), "r"(a3), "r"(b0), "r"(b1))

// ======== HMMA GEMM (3-term fp16 split): Ch = half((A@W) * dinv[row]) ========
// A: [M,256] fp32 row-major, W: [256,N] fp32 row-major. CTA tile 128x128,
// 8 warps, warp tile 64x32. BK=32 smem chunks, hi/lo operand split.
__global__ __launch_bounds__(256) void k_gemm_mma(
    const float* __restrict__ A, const float* __restrict__ W,
    const float* __restrict__ dinv, __half* __restrict__ Ch, int M, int N)
{
    constexpr int K = 256;
    constexpr int BK = 32;
    constexpr int LD = 40;                 // 32 + 8 pad halfs
    __shared__ __half As[2][128][LD];      // [hi/lo][m][k]
    __shared__ __half Bs[2][128][LD];      // [hi/lo][n][k]

    int tid = threadIdx.x;
    int w = tid >> 5;
    int lane = tid & 31;
    int gid = lane >> 2;
    int tig = lane & 3;
    int warp_m = w >> 2;                   // 0..1
    int warp_n = w & 3;                    // 0..3
    int row0 = blockIdx.y * 128;
    int col0 = blockIdx.x * 128;

    float acc[4][4][4];
#pragma unroll
    for (int mt = 0; mt < 4; mt++)
#pragma unroll
        for (int nt = 0; nt < 4; nt++)
#pragma unroll
            for (int q = 0; q < 4; q++) acc[mt][nt][q] = 0.f;

    for (int kt = 0; kt < K; kt += BK) {
        // A chunk: 128 rows x 32 k = 1024 float4, 4 per thread
#pragma unroll
        for (int i = 0; i < 4; i++) {
            int f = tid + i * 256;
            int r = f >> 3;
            int c = (f & 7) * 4;
            float4 v = make_float4(0.f, 0.f, 0.f, 0.f);
            int grow = row0 + r;
            if (grow < M) v = *(const float4*)(A + (size_t)grow * K + kt + c);
            float vv[4] = {v.x, v.y, v.z, v.w};
#pragma unroll
            for (int j = 0; j < 4; j++) {
                __half h, l;
                split_hl(vv[j], h, l);
                As[0][r][c + j] = h;
                As[1][r][c + j] = l;
            }
        }
        // B chunk: 32 k-rows x 128 cols, transposed into Bs[n][k]
#pragma unroll
        for (int i = 0; i < 4; i++) {
            int f = tid + i * 256;
            int k = f >> 5;
            int c = (f & 31) * 4;
            float4 v = *(const float4*)(W + (size_t)(kt + k) * N + col0 + c);
            float vv[4] = {v.x, v.y, v.z, v.w};
#pragma unroll
            for (int j = 0; j < 4; j++) {
                __half h, l;
                split_hl(vv[j], h, l);
                Bs[0][c + j][k] = h;
                Bs[1][c + j][k] = l;
            }
        }
        __syncthreads();

#pragma unroll
        for (int k2 = 0; k2 < BK; k2 += 16) {
            // b frags for 4 n-tiles (hi + lo)
            uint32_t bh[4][2], bl[4][2];
#pragma unroll
            for (int nt = 0; nt < 4; nt++) {
                int nb = warp_n * 32 + nt * 8 + gid;
                bh[nt][0] = *(const uint32_t*)&Bs[0][nb][k2 + tig * 2];
                bh[nt][1] = *(const uint32_t*)&Bs[0][nb][k2 + tig * 2 + 8];
                bl[nt][0] = *(const uint32_t*)&Bs[1][nb][k2 + tig * 2];
                bl[nt][1] = *(const uint32_t*)&Bs[1][nb][k2 + tig * 2 + 8];
            }
#pragma unroll
            for (int mt = 0; mt < 4; mt++) {
                int mb = warp_m * 64 + mt * 16;
                uint32_t ah[4], al[4];
                ah[0] = *(const uint32_t*)&As[0][mb + gid][k2 + tig * 2];
                ah[1] = *(const uint32_t*)&As[0][mb + gid + 8][k2 + tig * 2];
                ah[2] = *(const uint32_t*)&As[0][mb + gid][k2 + tig * 2 + 8];
                ah[3] = *(const uint32_t*)&As[0][mb + gid + 8][k2 + tig * 2 + 8];
                al[0] = *(const uint32_t*)&As[1][mb + gid][k2 + tig * 2];
                al[1] = *(const uint32_t*)&As[1][mb + gid + 8][k2 + tig * 2];
                al[2] = *(const uint32_t*)&As[1][mb + gid][k2 + tig * 2 + 8];
                al[3] = *(const uint32_t*)&As[1][mb + gid + 8][k2 + tig * 2 + 8];
#pragma unroll
                for (int nt = 0; nt < 4; nt++) {
                    MMA16816(acc[mt][nt], ah[0], ah[1], ah[2], ah[3], bh[nt][0], bh[nt][1]);
                    MMA16816(acc[mt][nt], ah[0], ah[1], ah[2], ah[3], bl[nt][0], bl[nt][1]);
                    MMA16816(acc[mt][nt], al[0], al[1], al[2], al[3], bh[nt][0], bh[nt][1]);
                }
            }
        }
        __syncthreads();
    }

    // epilogue: scale by dinv, store fp16 only
#pragma unroll
    for (int mt = 0; mt < 4; mt++) {
        int r0 = row0 + warp_m * 64 + mt * 16 + gid;
        int r1 = r0 + 8;
        float s0 = (r0 < M) ? dinv[r0] : 0.f;
        float s1 = (r1 < M) ? dinv[r1] : 0.f;
#pragma unroll
        for (int nt = 0; nt < 4; nt++) {
            int c = col0 + warp_n * 32 + nt * 8 + tig * 2;
            if (r0 < M) {
                __half2 h = __floats2half2_rn(acc[mt][nt][0] * s0, acc[mt][nt][1] * s0);
                *(__half2*)(Ch + (size_t)r0 * N + c) = h;
            }
            if (r1 < M) {
                __half2 h = __floats2half2_rn(acc[mt][nt][2] * s1, acc[mt][nt][3] * s1);
                *(__half2*)(Ch + (size_t)r1 * N + c) = h;
            }
        }
    }
}

// -------- CSR gather-reduce over fp16 features, fp32 accumulate --------
template <int FH, bool RELU>
__global__ __launch_bounds__(256) void k_gather_h(
    const int* __restrict__ off, const int* __restrict__ srcs,
    const __half* __restrict__ hsh, const float* __restrict__ dinv,
    const float* __restrict__ bias, float* __restrict__ out)
{
    constexpr int F = 32 * FH;
    int node = (blockIdx.x * blockDim.x + threadIdx.x) >> 5;
    int lane = threadIdx.x & 31;
    if (node >= NN) return;
    const __half* base = hsh + lane * FH;

    float acc[FH];
#pragma unroll
    for (int j = 0; j < FH; j++) acc[j] = 0.f;

    auto accum = [&](int s) {
        const __half* p = base + (size_t)s * F;
        if (FH == 8) {
            uint4 v = *(const uint4*)p;
            float2 f;
            f = __half22float2(*(__half2*)&v.x); acc[0] += f.x; acc[1] += f.y;
            f = __half22float2(*(__half2*)&v.y); acc[2] += f.x; acc[3] += f.y;
            f = __half22float2(*(__half2*)&v.z); acc[4] += f.x; acc[5] += f.y;
            f = __half22float2(*(__half2*)&v.w); acc[6] += f.x; acc[7] += f.y;
        } else {
            uint2 v = *(const uint2*)p;
            float2 f;
            f = __half22float2(*(__half2*)&v.x); acc[0] += f.x; acc[1] += f.y;
            f = __half22float2(*(__half2*)&v.y); acc[2] += f.x; acc[3] += f.y;
        }
    };

    accum(node);                                   // self loop
    int e = off[node], end = off[node + 1];
    for (; e + 4 <= end; e += 4) {
        int s0 = srcs[e], s1 = srcs[e + 1], s2 = srcs[e + 2], s3 = srcs[e + 3];
        accum(s0); accum(s1); accum(s2); accum(s3);
    }
    for (; e < end; e++) accum(srcs[e]);

    float sc = dinv[node];
    float* dst = out + (size_t)node * F + lane * FH;
    const float* bp = bias + lane * FH;
#pragma unroll
    for (int j = 0; j < FH; j += 4) {
        float4 b = *(const float4*)(bp + j);
        float4 o;
        o.x = sc * acc[j + 0] + b.x;
        o.y = sc * acc[j + 1] + b.y;
        o.z = sc * acc[j + 2] + b.z;
        o.w = sc * acc[j + 3] + b.w;
        if (RELU) {
            o.x = fmaxf(o.x, 0.f); o.y = fmaxf(o.y, 0.f);
            o.z = fmaxf(o.z, 0.f); o.w = fmaxf(o.w, 0.f);
        }
        *(float4*)(dst + j) = o;
    }
}

extern "C" void kernel_launch(void* const* d_in, const int* in_sizes, int n_in,
                              void* d_out, int out_size)
{
    const float* x  = (const float*)d_in[0];
    const void*  ei = d_in[1];
    const float* W1 = (const float*)d_in[2];
    const float* b1 = (const float*)d_in[3];
    const float* W2 = (const float*)d_in[4];
    const float* b2 = (const float*)d_in[5];
    const int E = in_sizes[1] / 2;
    const int n = NN;

    int *deg, *off, *cur, *srcs, *bsum;
    float *dinv, *h1;
    __half *hh1, *hh2;
    cudaGetSymbolAddress((void**)&deg,  g_deg);
    cudaGetSymbolAddress((void**)&off,  g_off);
    cudaGetSymbolAddress((void**)&cur,  g_cur);
    cudaGetSymbolAddress((void**)&srcs, g_srcs);
    cudaGetSymbolAddress((void**)&bsum, g_bsum);
    cudaGetSymbolAddress((void**)&dinv, g_dinv);
    cudaGetSymbolAddress((void**)&hh1,  g_hh1);
    cudaGetSymbolAddress((void**)&h1,   g_h1);
    cudaGetSymbolAddress((void**)&hh2,  g_hh2);

    // dtype sniff
    k_detect<<<1, 256>>>((const int*)ei, 8192);

    // degree -> parallel scan -> dinv -> CSR buckets
    k_zeroint<<<(n + 255) / 256, 256>>>(deg, n);
    k_edgedeg<<<(E + 255) / 256, 256>>>(ei, deg, E);
    k_scan1<<<NBLK, SCAN_B>>>(deg, off, bsum);
    k_scan2<<<1, 64>>>(bsum, off + NN);
    k_scan3<<<NBLK, SCAN_B>>>(off, cur, bsum, deg, dinv);
    k_bucket<<<(E + 255) / 256, 256>>>(ei, cur, srcs, E);

    const int MT = (n + 127) / 128;   // 391 row tiles

    // ---- layer 1 ----
    {
        dim3 grid(F1 / 128, MT);
        k_gemm_mma<<<grid, 256>>>(x, W1, dinv, hh1, n, F1);
    }
    k_gather_h<8, true><<<(n * 32 + 255) / 256, 256>>>(off, srcs, hh1, dinv, b1, h1);

    // ---- layer 2 ----
    {
        dim3 grid(F2 / 128, MT);
        k_gemm_mma<<<grid, 256>>>(h1, W2, dinv, hh2, n, F2);
    }
    k_gather_h<4, false><<<(n * 32 + 255) / 256, 256>>>(off, srcs, hh2, dinv, b2, (float*)d_out);
}

// round 7
// speedup vs baseline: 1.0016x; 1.0016x over previous
#include <cuda_runtime.h>
#include <cuda_fp16.h>
#include <cstdint>

#define NN 50000
#define F1 256
#define F2 128
#define EMAX 2000000
#define SCAN_B 1024
#define NBLK ((NN + SCAN_B - 1) / SCAN_B)   // 49

// -------- scratch (static device globals; no allocation) --------
__device__ int g_deg[NN];
__device__ int g_off[NN + 1];
__device__ int g_cur[NN];
__device__ int g_bsum[NBLK];
__device__ int g_srcs[EMAX];
__device__ __align__(16) float  g_dinv[NN];
__device__ __align__(16) __half g_hh1[(size_t)NN * F1];   // fp16 (x@W1)*dinv
__device__ __align__(16) float  g_h1[(size_t)NN * F1];    // relu'd layer-1 out (fp32)
__device__ __align__(16) __half g_hh2[(size_t)NN * F2];   // fp16 (h1@W2)*dinv
__device__ int g_is64;

// -------- packed f32x2 helpers --------
#define PACKF2(d, lo, hi) \
    asm("mov.b64 %0, {%1, %2};" : "=l"(d) : "f"(lo), "f"(hi))
#define UNPACKF2(lo, hi, s) \
    asm("mov.b64 {%0, %1}, %2;" : "=f"(lo), "=f"(hi) : "l"(s))
#define FMAF2(acc, a, b) \
    asm("fma.rn.f32x2 %0, %1, %2, %0;" : "+l"(acc) : "l"(a), "l"(b))

#define MMA16816(d, a0, a1, a2, a3, b0, b1)                                   \
    asm volatile(                                                             \
        "mma.sync.aligned.m16n8k16.row.col.f32.f16.f16.f32 "                  \
        "{%0,%1,%2,%3}, {%4,%5,%6,%7}, {%8,%9}, {%0,%1,%2,%3};"               \
        : "+f"((d)[0]), "+f"((d)[1]), "+f"((d)[2]), "+f"((d)[3])              \
        : "r"(a0), "r"(a1), "r"(a2), "r"(a3), "r"(b0), "r"(b1))

// -------- edge dtype detection (int64 vs int32) --------
__global__ void k_detect(const int* __restrict__ w, int nwords) {
    __shared__ int ok;
    if (threadIdx.x == 0) ok = 1;
    __syncthreads();
    for (int i = threadIdx.x; i < nwords / 2; i += blockDim.x)
        if (w[2 * i + 1] != 0) ok = 0;   // benign race
    __syncthreads();
    if (threadIdx.x == 0) g_is64 = ok;
}
__device__ __forceinline__ int edge_at(const void* p, int i, int is64) {
    if (is64) return (int)((const long long*)p)[i];
    return ((const int*)p)[i];
}

__global__ void k_zeroint(int* __restrict__ p, int n) {
    int i = blockIdx.x * blockDim.x + threadIdx.x;
    if (i < n) p[i] = 0;
}
__global__ void k_edgedeg(const void* __restrict__ ei, int* __restrict__ deg, int E) {
    int i = blockIdx.x * blockDim.x + threadIdx.x;
    if (i >= E) return;
    int d = edge_at(ei, E + i, g_is64);
    atomicAdd(deg + d, 1);
}

// -------- 3-phase parallel exclusive scan --------
__global__ __launch_bounds__(SCAN_B) void k_scan1(
    const int* __restrict__ deg, int* __restrict__ off, int* __restrict__ bsum)
{
    __shared__ int sh[SCAN_B];
    int t = threadIdx.x;
    int idx = blockIdx.x * SCAN_B + t;
    int v = (idx < NN) ? deg[idx] : 0;
    sh[t] = v;
    __syncthreads();
#pragma unroll
    for (int d = 1; d < SCAN_B; d <<= 1) {
        int u = 0;
        if (t >= d) u = sh[t - d];
        __syncthreads();
        if (t >= d) sh[t] += u;
        __syncthreads();
    }
    if (idx < NN) off[idx] = sh[t] - v;
    if (t == SCAN_B - 1) bsum[blockIdx.x] = sh[t];
}
__global__ void k_scan2(int* __restrict__ bsum, int* __restrict__ off_last) {
    __shared__ int sh[64];
    int t = threadIdx.x;
    int v = (t < NBLK) ? bsum[t] : 0;
    sh[t] = v;
    __syncthreads();
#pragma unroll
    for (int d = 1; d < 64; d <<= 1) {
        int u = 0;
        if (t >= d) u = sh[t - d];
        __syncthreads();
        if (t >= d) sh[t] += u;
        __syncthreads();
    }
    if (t < NBLK) bsum[t] = sh[t] - v;
    if (t == 63) *off_last = sh[63];
}
__global__ void k_scan3(int* __restrict__ off, int* __restrict__ cur,
                        const int* __restrict__ bsum, const int* __restrict__ deg,
                        float* __restrict__ dinv)
{
    int idx = blockIdx.x * SCAN_B + threadIdx.x;
    if (idx >= NN) return;
    int o = off[idx] + bsum[blockIdx.x];
    off[idx] = o;
    cur[idx] = o;
    dinv[idx] = rsqrtf((float)deg[idx] + 1.0f);
}

__global__ void k_bucket(const void* __restrict__ ei, int* __restrict__ cur,
                         int* __restrict__ srcs, int E) {
    int i = blockIdx.x * blockDim.x + threadIdx.x;
    if (i >= E) return;
    int is64 = g_is64;
    int s = edge_at(ei, i, is64);
    int d = edge_at(ei, E + i, is64);
    int p = atomicAdd(cur + d, 1);
    srcs[p] = s;
}

__device__ __forceinline__ void split_hl(float v, __half& h, __half& l) {
    h = __float2half_rn(v);
    l = __float2half_rn(v - __half2float(h));
}

// ======== HYBRID GEMM: Ch = half((A@W) * dinv[row]),  K = 256 ========
// Each 128x128 tile block runs either the FFMA (fma-pipe) or HMMA (tensor-pipe)
// path. Path chosen by wave slot (bid/148) so co-resident CTAs on one SM use
// DIFFERENT pipes and run concurrently.
__global__ __launch_bounds__(256) void k_gemm_hybrid(
    const float* __restrict__ A, const float* __restrict__ W,
    const float* __restrict__ dinv, __half* __restrict__ Ch, int M, int N)
{
    constexpr int K = 256;
    extern __shared__ char sm[];
    int tid = threadIdx.x;
    int bid = blockIdx.x + blockIdx.y * gridDim.x;
    int row0 = blockIdx.y * 128;
    int col0 = blockIdx.x * 128;
    bool use_ffma = (((bid / 148) & 1) == 0);

    if (use_ffma) {
        // ---------- FFMA path: BK=16, 256 thr, 8x8/thread (f32x2 packed) ----------
        float (*As)[128] = (float(*)[128])sm;            // [16][128] transposed
        float (*Bs)[128] = (float(*)[128])(sm + 8192);
        int tx = tid & 15;
        int ty = tid >> 4;

        unsigned long long acc[8][4];
#pragma unroll
        for (int i = 0; i < 8; i++)
#pragma unroll
            for (int j = 0; j < 4; j++) acc[i][j] = 0ULL;

        for (int kt = 0; kt < K; kt += 16) {
#pragma unroll
            for (int i = 0; i < 2; i++) {
                int f = tid * 2 + i;
                int r = f >> 2;
                int c = (f & 3) * 4;
                float4 v = make_float4(0.f, 0.f, 0.f, 0.f);
                int grow = row0 + r;
                if (grow < M) v = *(const float4*)(A + (size_t)grow * K + kt + c);
                As[c + 0][r] = v.x; As[c + 1][r] = v.y;
                As[c + 2][r] = v.z; As[c + 3][r] = v.w;
            }
#pragma unroll
            for (int i = 0; i < 2; i++) {
                int f = tid * 2 + i;
                int r = f >> 5;
                int c = (f & 31) * 4;
                *(float4*)&Bs[r][c] = *(const float4*)(W + (size_t)(kt + r) * N + col0 + c);
            }
            __syncthreads();
#pragma unroll
            for (int k = 0; k < 16; k++) {
                float4 a0 = *(const float4*)&As[k][ty * 4];
                float4 a1 = *(const float4*)&As[k][ty * 4 + 64];
                float4 b0 = *(const float4*)&Bs[k][tx * 4];
                float4 b1 = *(const float4*)&Bs[k][tx * 4 + 64];
                unsigned long long bp[4];
                PACKF2(bp[0], b0.x, b0.y);
                PACKF2(bp[1], b0.z, b0.w);
                PACKF2(bp[2], b1.x, b1.y);
                PACKF2(bp[3], b1.z, b1.w);
                float av[8] = {a0.x, a0.y, a0.z, a0.w, a1.x, a1.y, a1.z, a1.w};
#pragma unroll
                for (int i = 0; i < 8; i++) {
                    unsigned long long ap;
                    PACKF2(ap, av[i], av[i]);
#pragma unroll
                    for (int j = 0; j < 4; j++)
                        FMAF2(acc[i][j], ap, bp[j]);
                }
            }
            __syncthreads();
        }
#pragma unroll
        for (int half = 0; half < 2; half++) {
#pragma unroll
            for (int i = 0; i < 4; i++) {
                int grow = row0 + half * 64 + ty * 4 + i;
                if (grow >= M) continue;
                float s = dinv[grow];
                int ai = half * 4 + i;
#pragma unroll
                for (int ch = 0; ch < 2; ch++) {
                    float4 v;
                    UNPACKF2(v.x, v.y, acc[ai][ch * 2 + 0]);
                    UNPACKF2(v.z, v.w, acc[ai][ch * 2 + 1]);
                    __half2 h0 = __floats2half2_rn(v.x * s, v.y * s);
                    __half2 h1 = __floats2half2_rn(v.z * s, v.w * s);
                    uint2 hp;
                    hp.x = *(uint32_t*)&h0;
                    hp.y = *(uint32_t*)&h1;
                    *(uint2*)(Ch + (size_t)grow * N + col0 + ch * 64 + tx * 4) = hp;
                }
            }
        }
    } else {
        // ---------- HMMA path: BK=32, 8 warps, 64x32 warp tile, 3-term split ----------
        constexpr int BK = 32;
        constexpr int LD = 40;                    // 32 + 8 pad halfs
        __half* AsH = (__half*)sm;                // [128][40]
        __half* AsL = AsH + 128 * LD;
        __half* BsH = AsL + 128 * LD;
        __half* BsL = BsH + 128 * LD;

        int w = tid >> 5;
        int lane = tid & 31;
        int gid = lane >> 2;
        int tig = lane & 3;
        int warp_m = w >> 2;
        int warp_n = w & 3;

        float acc[4][4][4];
#pragma unroll
        for (int mt = 0; mt < 4; mt++)
#pragma unroll
            for (int nt = 0; nt < 4; nt++)
#pragma unroll
                for (int q = 0; q < 4; q++) acc[mt][nt][q] = 0.f;

        for (int kt = 0; kt < K; kt += BK) {
#pragma unroll
            for (int i = 0; i < 4; i++) {
                int f = tid + i * 256;
                int r = f >> 3;
                int c = (f & 7) * 4;
                float4 v = make_float4(0.f, 0.f, 0.f, 0.f);
                int grow = row0 + r;
                if (grow < M) v = *(const float4*)(A + (size_t)grow * K + kt + c);
                float vv[4] = {v.x, v.y, v.z, v.w};
#pragma unroll
                for (int j = 0; j < 4; j++) {
                    __half h, l;
                    split_hl(vv[j], h, l);
                    AsH[r * LD + c + j] = h;
                    AsL[r * LD + c + j] = l;
                }
            }
#pragma unroll
            for (int i = 0; i < 4; i++) {
                int f = tid + i * 256;
                int k = f >> 5;
                int c = (f & 31) * 4;
                float4 v = *(const float4*)(W + (size_t)(kt + k) * N + col0 + c);
                float vv[4] = {v.x, v.y, v.z, v.w};
#pragma unroll
                for (int j = 0; j < 4; j++) {
                    __half h, l;
                    split_hl(vv[j], h, l);
                    BsH[(c + j) * LD + k] = h;
                    BsL[(c + j) * LD + k] = l;
                }
            }
            __syncthreads();

#pragma unroll
            for (int k2 = 0; k2 < BK; k2 += 16) {
                uint32_t bh[4][2], bl[4][2];
#pragma unroll
                for (int nt = 0; nt < 4; nt++) {
                    int nb = warp_n * 32 + nt * 8 + gid;
                    bh[nt][0] = *(const uint32_t*)&BsH[nb * LD + k2 + tig * 2];
                    bh[nt][1] = *(const uint32_t*)&BsH[nb * LD + k2 + tig * 2 + 8];
                    bl[nt][0] = *(const uint32_t*)&BsL[nb * LD + k2 + tig * 2];
                    bl[nt][1] = *(const uint32_t*)&BsL[nb * LD + k2 + tig * 2 + 8];
                }
#pragma unroll
                for (int mt = 0; mt < 4; mt++) {
                    int mb = warp_m * 64 + mt * 16;
                    uint32_t ah[4], al[4];
                    ah[0] = *(const uint32_t*)&AsH[(mb + gid) * LD + k2 + tig * 2];
                    ah[1] = *(const uint32_t*)&AsH[(mb + gid + 8) * LD + k2 + tig * 2];
                    ah[2] = *(const uint32_t*)&AsH[(mb + gid) * LD + k2 + tig * 2 + 8];
                    ah[3] = *(const uint32_t*)&AsH[(mb + gid + 8) * LD + k2 + tig * 2 + 8];
                    al[0] = *(const uint32_t*)&AsL[(mb + gid) * LD + k2 + tig * 2];
                    al[1] = *(const uint32_t*)&AsL[(mb + gid + 8) * LD + k2 + tig * 2];
                    al[2] = *(const uint32_t*)&AsL[(mb + gid) * LD + k2 + tig * 2 + 8];
                    al[3] = *(const uint32_t*)&AsL[(mb + gid + 8) * LD + k2 + tig * 2 + 8];
#pragma unroll
                    for (int nt = 0; nt < 4; nt++) {
                        MMA16816(acc[mt][nt], ah[0], ah[1], ah[2], ah[3], bh[nt][0], bh[nt][1]);
                        MMA16816(acc[mt][nt], ah[0], ah[1], ah[2], ah[3], bl[nt][0], bl[nt][1]);
                        MMA16816(acc[mt][nt], al[0], al[1], al[2], al[3], bh[nt][0], bh[nt][1]);
                    }
                }
            }
            __syncthreads();
        }

#pragma unroll
        for (int mt = 0; mt < 4; mt++) {
            int r0 = row0 + warp_m * 64 + mt * 16 + gid;
            int r1 = r0 + 8;
            float s0 = (r0 < M) ? dinv[r0] : 0.f;
            float s1 = (r1 < M) ? dinv[r1] : 0.f;
#pragma unroll
            for (int nt = 0; nt < 4; nt++) {
                int c = col0 + warp_n * 32 + nt * 8 + tig * 2;
                if (r0 < M) {
                    __half2 h = __floats2half2_rn(acc[mt][nt][0] * s0, acc[mt][nt][1] * s0);
                    *(__half2*)(Ch + (size_t)r0 * N + c) = h;
                }
                if (r1 < M) {
                    __half2 h = __floats2half2_rn(acc[mt][nt][2] * s1, acc[mt][nt][3] * s1);
                    *(__half2*)(Ch + (size_t)r1 * N + c) = h;
                }
            }
        }
    }
}

// -------- CSR gather-reduce over fp16 features, fp32 accumulate --------
template <int FH, bool RELU>
__global__ __launch_bounds__(256) void k_gather_h(
    const int* __restrict__ off, const int* __restrict__ srcs,
    const __half* __restrict__ hsh, const float* __restrict__ dinv,
    const float* __restrict__ bias, float* __restrict__ out)
{
    constexpr int F = 32 * FH;
    int node = (blockIdx.x * blockDim.x + threadIdx.x) >> 5;
    int lane = threadIdx.x & 31;
    if (node >= NN) return;
    const __half* base = hsh + lane * FH;

    float acc[FH];
#pragma unroll
    for (int j = 0; j < FH; j++) acc[j] = 0.f;

    auto accum = [&](int s) {
        const __half* p = base + (size_t)s * F;
        if (FH == 8) {
            uint4 v = *(const uint4*)p;
            float2 f;
            f = __half22float2(*(__half2*)&v.x); acc[0] += f.x; acc[1] += f.y;
            f = __half22float2(*(__half2*)&v.y); acc[2] += f.x; acc[3] += f.y;
            f = __half22float2(*(__half2*)&v.z); acc[4] += f.x; acc[5] += f.y;
            f = __half22float2(*(__half2*)&v.w); acc[6] += f.x; acc[7] += f.y;
        } else {
            uint2 v = *(const uint2*)p;
            float2 f;
            f = __half22float2(*(__half2*)&v.x); acc[0] += f.x; acc[1] += f.y;
            f = __half22float2(*(__half2*)&v.y); acc[2] += f.x; acc[3] += f.y;
        }
    };

    accum(node);                                   // self loop
    int e = off[node], end = off[node + 1];
    for (; e + 4 <= end; e += 4) {
        int s0 = srcs[e], s1 = srcs[e + 1], s2 = srcs[e + 2], s3 = srcs[e + 3];
        accum(s0); accum(s1); accum(s2); accum(s3);
    }
    for (; e < end; e++) accum(srcs[e]);

    float sc = dinv[node];
    float* dst = out + (size_t)node * F + lane * FH;
    const float* bp = bias + lane * FH;
#pragma unroll
    for (int j = 0; j < FH; j += 4) {
        float4 b = *(const float4*)(bp + j);
        float4 o;
        o.x = sc * acc[j + 0] + b.x;
        o.y = sc * acc[j + 1] + b.y;
        o.z = sc * acc[j + 2] + b.z;
        o.w = sc * acc[j + 3] + b.w;
        if (RELU) {
            o.x = fmaxf(o.x, 0.f); o.y = fmaxf(o.y, 0.f);
            o.z = fmaxf(o.z, 0.f); o.w = fmaxf(o.w, 0.f);
        }
        *(float4*)(dst + j) = o;
    }
}

extern "C" void kernel_launch(void* const* d_in, const int* in_sizes, int n_in,
                              void* d_out, int out_size)
{
    const float* x  = (const float*)d_in[0];
    const void*  ei = d_in[1];
    const float* W1 = (const float*)d_in[2];
    const float* b1 = (const float*)d_in[3];
    const float* W2 = (const float*)d_in[4];
    const float* b2 = (const float*)d_in[5];
    const int E = in_sizes[1] / 2;
    const int n = NN;

    int *deg, *off, *cur, *srcs, *bsum;
    float *dinv, *h1;
    __half *hh1, *hh2;
    cudaGetSymbolAddress((void**)&deg,  g_deg);
    cudaGetSymbolAddress((void**)&off,  g_off);
    cudaGetSymbolAddress((void**)&cur,  g_cur);
    cudaGetSymbolAddress((void**)&srcs, g_srcs);
    cudaGetSymbolAddress((void**)&bsum, g_bsum);
    cudaGetSymbolAddress((void**)&dinv, g_dinv);
    cudaGetSymbolAddress((void**)&hh1,  g_hh1);
    cudaGetSymbolAddress((void**)&h1,   g_h1);
    cudaGetSymbolAddress((void**)&hh2,  g_hh2);

    const int HYB_SMEM = 4 * 128 * 40 * 2;   // 40960 B (HMMA layout; FFMA uses 16KB of it)

    // dtype sniff
    k_detect<<<1, 256>>>((const int*)ei, 8192);

    // degree -> parallel scan -> dinv -> CSR buckets
    k_zeroint<<<(n + 255) / 256, 256>>>(deg, n);
    k_edgedeg<<<(E + 255) / 256, 256>>>(ei, deg, E);
    k_scan1<<<NBLK, SCAN_B>>>(deg, off, bsum);
    k_scan2<<<1, 64>>>(bsum, off + NN);
    k_scan3<<<NBLK, SCAN_B>>>(off, cur, bsum, deg, dinv);
    k_bucket<<<(E + 255) / 256, 256>>>(ei, cur, srcs, E);

    const int MT = (n + 127) / 128;   // 391 row tiles

    // ---- layer 1 ----
    {
        dim3 grid(F1 / 128, MT);
        k_gemm_hybrid<<<grid, 256, HYB_SMEM>>>(x, W1, dinv, hh1, n, F1);
    }
    k_gather_h<8, true><<<(n * 32 + 255) / 256, 256>>>(off, srcs, hh1, dinv, b1, h1);

    // ---- layer 2 ----
    {
        dim3 grid(F2 / 128, MT);
        k_gemm_hybrid<<<grid, 256, HYB_SMEM>>>(h1, W2, dinv, hh2, n, F2);
    }
    k_gather_h<4, false><<<(n * 32 + 255) / 256, 256>>>(off, srcs, hh2, dinv, b2, (float*)d_out);
}

// round 8
// speedup vs baseline: 1.4719x; 1.4695x over previous
#include <cuda_runtime.h>
#include <cuda_fp16.h>
#include <cstdint>

#define NN 50000
#define F1 256
#define F2 128
#define EMAX 2000000
#define SCAN_B 1024
#define NBLK ((NN + SCAN_B - 1) / SCAN_B)   // 49

// -------- scratch (static device globals; no allocation) --------
__device__ int g_deg[NN];
__device__ int g_off[NN + 1];
__device__ int g_cur[NN];
__device__ int g_bsum[NBLK];
__device__ int g_srcs[EMAX];
__device__ __align__(16) float  g_dinv[NN];
__device__ __align__(16) __half g_hh1[(size_t)NN * F1];   // fp16 (x@W1)*dinv
__device__ __align__(16) float  g_h1[(size_t)NN * F1];    // relu'd layer-1 out (fp32)
__device__ __align__(16) __half g_hh2[(size_t)NN * F2];   // fp16 (h1@W2)*dinv
__device__ int g_is64;

#define MMA16816(d, a0, a1, a2, a3, b0, b1)                                   \
    asm volatile(                                                             \
        "mma.sync.aligned.m16n8k16.row.col.f32.f16.f16.f32 "                  \
        "{%0,%1,%2,%3}, {%4,%5,%6,%7}, {%8,%9}, {%0,%1,%2,%3};"               \
        : "+f"((d)[0]), "+f"((d)[1]), "+f"((d)[2]), "+f"((d)[3])              \
        : "r"(a0), "r"(a1), "r"(a2), "r"(a3), "r"(b0), "r"(b1))

// -------- edge dtype detection (int64 vs int32) --------
__global__ void k_detect(const int* __restrict__ w, int nwords) {
    __shared__ int ok;
    if (threadIdx.x == 0) ok = 1;
    __syncthreads();
    for (int i = threadIdx.x; i < nwords / 2; i += blockDim.x)
        if (w[2 * i + 1] != 0) ok = 0;   // benign race
    __syncthreads();
    if (threadIdx.x == 0) g_is64 = ok;
}
__device__ __forceinline__ int edge_at(const void* p, int i, int is64) {
    if (is64) return (int)((const long long*)p)[i];
    return ((const int*)p)[i];
}

__global__ void k_zeroint(int* __restrict__ p, int n) {
    int i = blockIdx.x * blockDim.x + threadIdx.x;
    if (i < n) p[i] = 0;
}
__global__ void k_edgedeg(const void* __restrict__ ei, int* __restrict__ deg, int E) {
    int i = blockIdx.x * blockDim.x + threadIdx.x;
    if (i >= E) return;
    int d = edge_at(ei, E + i, g_is64);
    atomicAdd(deg + d, 1);
}

// -------- 3-phase parallel exclusive scan --------
__global__ __launch_bounds__(SCAN_B) void k_scan1(
    const int* __restrict__ deg, int* __restrict__ off, int* __restrict__ bsum)
{
    __shared__ int sh[SCAN_B];
    int t = threadIdx.x;
    int idx = blockIdx.x * SCAN_B + t;
    int v = (idx < NN) ? deg[idx] : 0;
    sh[t] = v;
    __syncthreads();
#pragma unroll
    for (int d = 1; d < SCAN_B; d <<= 1) {
        int u = 0;
        if (t >= d) u = sh[t - d];
        __syncthreads();
        if (t >= d) sh[t] += u;
        __syncthreads();
    }
    if (idx < NN) off[idx] = sh[t] - v;
    if (t == SCAN_B - 1) bsum[blockIdx.x] = sh[t];
}
__global__ void k_scan2(int* __restrict__ bsum, int* __restrict__ off_last) {
    __shared__ int sh[64];
    int t = threadIdx.x;
    int v = (t < NBLK) ? bsum[t] : 0;
    sh[t] = v;
    __syncthreads();
#pragma unroll
    for (int d = 1; d < 64; d <<= 1) {
        int u = 0;
        if (t >= d) u = sh[t - d];
        __syncthreads();
        if (t >= d) sh[t] += u;
        __syncthreads();
    }
    if (t < NBLK) bsum[t] = sh[t] - v;
    if (t == 63) *off_last = sh[63];
}
__global__ void k_scan3(int* __restrict__ off, int* __restrict__ cur,
                        const int* __restrict__ bsum, const int* __restrict__ deg,
                        float* __restrict__ dinv)
{
    int idx = blockIdx.x * SCAN_B + threadIdx.x;
    if (idx >= NN) return;
    int o = off[idx] + bsum[blockIdx.x];
    off[idx] = o;
    cur[idx] = o;
    dinv[idx] = rsqrtf((float)deg[idx] + 1.0f);
}

__global__ void k_bucket(const void* __restrict__ ei, int* __restrict__ cur,
                         int* __restrict__ srcs, int E) {
    int i = blockIdx.x * blockDim.x + threadIdx.x;
    if (i >= E) return;
    int is64 = g_is64;
    int s = edge_at(ei, i, is64);
    int d = edge_at(ei, E + i, is64);
    int p = atomicAdd(cur + d, 1);
    srcs[p] = s;
}

// ======== HMMA GEMM (single-term fp16): Ch = half((A@W) * dinv[row]) ========
// A: [M,256] fp32 row-major, W: [256,N] fp32 row-major. CTA tile 128x128,
// 8 warps, warp tile 64x32, BK=32. Operands rounded to fp16 once; fp32 accum.
__global__ __launch_bounds__(256) void k_gemm_mma(
    const float* __restrict__ A, const float* __restrict__ W,
    const float* __restrict__ dinv, __half* __restrict__ Ch, int M, int N)
{
    constexpr int K = 256;
    constexpr int BK = 32;
    constexpr int LD = 40;                 // 32 + 8 pad halfs
    __shared__ __half As[128][LD];         // [m][k]
    __shared__ __half Bs[128][LD];         // [n][k]

    int tid = threadIdx.x;
    int w = tid >> 5;
    int lane = tid & 31;
    int gid = lane >> 2;
    int tig = lane & 3;
    int warp_m = w >> 2;                   // 0..1
    int warp_n = w & 3;                    // 0..3
    int row0 = blockIdx.y * 128;
    int col0 = blockIdx.x * 128;

    float acc[4][4][4];
#pragma unroll
    for (int mt = 0; mt < 4; mt++)
#pragma unroll
        for (int nt = 0; nt < 4; nt++)
#pragma unroll
            for (int q = 0; q < 4; q++) acc[mt][nt][q] = 0.f;

    for (int kt = 0; kt < K; kt += BK) {
        // A chunk: 128 rows x 32 k = 1024 float4, 4 per thread
#pragma unroll
        for (int i = 0; i < 4; i++) {
            int f = tid + i * 256;
            int r = f >> 3;
            int c = (f & 7) * 4;
            float4 v = make_float4(0.f, 0.f, 0.f, 0.f);
            int grow = row0 + r;
            if (grow < M) v = *(const float4*)(A + (size_t)grow * K + kt + c);
            __half2 h0 = __floats2half2_rn(v.x, v.y);
            __half2 h1 = __floats2half2_rn(v.z, v.w);
            *(__half2*)&As[r][c]     = h0;
            *(__half2*)&As[r][c + 2] = h1;
        }
        // B chunk: 32 k-rows x 128 cols, transposed into Bs[n][k]
#pragma unroll
        for (int i = 0; i < 4; i++) {
            int f = tid + i * 256;
            int k = f >> 5;
            int c = (f & 31) * 4;
            float4 v = *(const float4*)(W + (size_t)(kt + k) * N + col0 + c);
            Bs[c + 0][k] = __float2half_rn(v.x);
            Bs[c + 1][k] = __float2half_rn(v.y);
            Bs[c + 2][k] = __float2half_rn(v.z);
            Bs[c + 3][k] = __float2half_rn(v.w);
        }
        __syncthreads();

#pragma unroll
        for (int k2 = 0; k2 < BK; k2 += 16) {
            uint32_t bf[4][2];
#pragma unroll
            for (int nt = 0; nt < 4; nt++) {
                int nb = warp_n * 32 + nt * 8 + gid;
                bf[nt][0] = *(const uint32_t*)&Bs[nb][k2 + tig * 2];
                bf[nt][1] = *(const uint32_t*)&Bs[nb][k2 + tig * 2 + 8];
            }
#pragma unroll
            for (int mt = 0; mt < 4; mt++) {
                int mb = warp_m * 64 + mt * 16;
                uint32_t af[4];
                af[0] = *(const uint32_t*)&As[mb + gid][k2 + tig * 2];
                af[1] = *(const uint32_t*)&As[mb + gid + 8][k2 + tig * 2];
                af[2] = *(const uint32_t*)&As[mb + gid][k2 + tig * 2 + 8];
                af[3] = *(const uint32_t*)&As[mb + gid + 8][k2 + tig * 2 + 8];
#pragma unroll
                for (int nt = 0; nt < 4; nt++)
                    MMA16816(acc[mt][nt], af[0], af[1], af[2], af[3], bf[nt][0], bf[nt][1]);
            }
        }
        __syncthreads();
    }

    // epilogue: scale by dinv, store fp16
#pragma unroll
    for (int mt = 0; mt < 4; mt++) {
        int r0 = row0 + warp_m * 64 + mt * 16 + gid;
        int r1 = r0 + 8;
        float s0 = (r0 < M) ? dinv[r0] : 0.f;
        float s1 = (r1 < M) ? dinv[r1] : 0.f;
#pragma unroll
        for (int nt = 0; nt < 4; nt++) {
            int c = col0 + warp_n * 32 + nt * 8 + tig * 2;
            if (r0 < M) {
                __half2 h = __floats2half2_rn(acc[mt][nt][0] * s0, acc[mt][nt][1] * s0);
                *(__half2*)(Ch + (size_t)r0 * N + c) = h;
            }
            if (r1 < M) {
                __half2 h = __floats2half2_rn(acc[mt][nt][2] * s1, acc[mt][nt][3] * s1);
                *(__half2*)(Ch + (size_t)r1 * N + c) = h;
            }
        }
    }
}

// -------- CSR gather-reduce over fp16 features, fp32 accumulate --------
template <int FH, bool RELU>
__global__ __launch_bounds__(256) void k_gather_h(
    const int* __restrict__ off, const int* __restrict__ srcs,
    const __half* __restrict__ hsh, const float* __restrict__ dinv,
    const float* __restrict__ bias, float* __restrict__ out)
{
    constexpr int F = 32 * FH;
    int node = (blockIdx.x * blockDim.x + threadIdx.x) >> 5;
    int lane = threadIdx.x & 31;
    if (node >= NN) return;
    const __half* base = hsh + lane * FH;

    float acc[FH];
#pragma unroll
    for (int j = 0; j < FH; j++) acc[j] = 0.f;

    auto accum = [&](int s) {
        const __half* p = base + (size_t)s * F;
        if (FH == 8) {
            uint4 v = *(const uint4*)p;
            float2 f;
            f = __half22float2(*(__half2*)&v.x); acc[0] += f.x; acc[1] += f.y;
            f = __half22float2(*(__half2*)&v.y); acc[2] += f.x; acc[3] += f.y;
            f = __half22float2(*(__half2*)&v.z); acc[4] += f.x; acc[5] += f.y;
            f = __half22float2(*(__half2*)&v.w); acc[6] += f.x; acc[7] += f.y;
        } else {
            uint2 v = *(const uint2*)p;
            float2 f;
            f = __half22float2(*(__half2*)&v.x); acc[0] += f.x; acc[1] += f.y;
            f = __half22float2(*(__half2*)&v.y); acc[2] += f.x; acc[3] += f.y;
        }
    };

    accum(node);                                   // self loop
    int e = off[node], end = off[node + 1];
    for (; e + 4 <= end; e += 4) {
        int s0 = srcs[e], s1 = srcs[e + 1], s2 = srcs[e + 2], s3 = srcs[e + 3];
        accum(s0); accum(s1); accum(s2); accum(s3);
    }
    for (; e < end; e++) accum(srcs[e]);

    float sc = dinv[node];
    float* dst = out + (size_t)node * F + lane * FH;
    const float* bp = bias + lane * FH;
#pragma unroll
    for (int j = 0; j < FH; j += 4) {
        float4 b = *(const float4*)(bp + j);
        float4 o;
        o.x = sc * acc[j + 0] + b.x;
        o.y = sc * acc[j + 1] + b.y;
        o.z = sc * acc[j + 2] + b.z;
        o.w = sc * acc[j + 3] + b.w;
        if (RELU) {
            o.x = fmaxf(o.x, 0.f); o.y = fmaxf(o.y, 0.f);
            o.z = fmaxf(o.z, 0.f); o.w = fmaxf(o.w, 0.f);
        }
        *(float4*)(dst + j) = o;
    }
}

extern "C" void kernel_launch(void* const* d_in, const int* in_sizes, int n_in,
                              void* d_out, int out_size)
{
    const float* x  = (const float*)d_in[0];
    const void*  ei = d_in[1];
    const float* W1 = (const float*)d_in[2];
    const float* b1 = (const float*)d_in[3];
    const float* W2 = (const float*)d_in[4];
    const float* b2 = (const float*)d_in[5];
    const int E = in_sizes[1] / 2;
    const int n = NN;

    int *deg, *off, *cur, *srcs, *bsum;
    float *dinv, *h1;
    __half *hh1, *hh2;
    cudaGetSymbolAddress((void**)&deg,  g_deg);
    cudaGetSymbolAddress((void**)&off,  g_off);
    cudaGetSymbolAddress((void**)&cur,  g_cur);
    cudaGetSymbolAddress((void**)&srcs, g_srcs);
    cudaGetSymbolAddress((void**)&bsum, g_bsum);
    cudaGetSymbolAddress((void**)&dinv, g_dinv);
    cudaGetSymbolAddress((void**)&hh1,  g_hh1);
    cudaGetSymbolAddress((void**)&h1,   g_h1);
    cudaGetSymbolAddress((void**)&hh2,  g_hh2);

    // dtype sniff
    k_detect<<<1, 256>>>((const int*)ei, 8192);

    // degree -> parallel scan -> dinv -> CSR buckets
    k_zeroint<<<(n + 255) / 256, 256>>>(deg, n);
    k_edgedeg<<<(E + 255) / 256, 256>>>(ei, deg, E);
    k_scan1<<<NBLK, SCAN_B>>>(deg, off, bsum);
    k_scan2<<<1, 64>>>(bsum, off + NN);
    k_scan3<<<NBLK, SCAN_B>>>(off, cur, bsum, deg, dinv);
    k_bucket<<<(E + 255) / 256, 256>>>(ei, cur, srcs, E);

    const int MT = (n + 127) / 128;   // 391 row tiles

    // ---- layer 1 ----
    {
        dim3 grid(F1 / 128, MT);
        k_gemm_mma<<<grid, 256>>>(x, W1, dinv, hh1, n, F1);
    }
    k_gather_h<8, true><<<(n * 32 + 255) / 256, 256>>>(off, srcs, hh1, dinv, b1, h1);

    // ---- layer 2 ----
    {
        dim3 grid(F2 / 128, MT);
        k_gemm_mma<<<grid, 256>>>(h1, W2, dinv, hh2, n, F2);
    }
    k_gather_h<4, false><<<(n * 32 + 255) / 256, 256>>>(off, srcs, hh2, dinv, b2, (float*)d_out);
}

// round 9
// speedup vs baseline: 2.1097x; 1.4333x over previous
#include <cuda_runtime.h>
#include <cuda_fp16.h>
#include <cstdint>

#define NN 50000
#define F1 256
#define F2 128
#define EMAX 2000000
#define SCAN_B 1024
#define NBLK ((NN + SCAN_B - 1) / SCAN_B)   // 49

// -------- scratch (static device globals; no allocation) --------
__device__ int g_deg[NN];
__device__ int g_off[NN + 1];
__device__ int g_cur[NN];
__device__ int g_bsum[NBLK];
__device__ int g_srcs[EMAX];
__device__ __align__(16) float  g_dinv[NN];
__device__ __align__(16) __half g_hx [(size_t)NN * F1];   // fp16 x
__device__ __align__(16) __half g_hw1[256 * F1];          // fp16 W1
__device__ __align__(16) __half g_hw2[256 * F2];          // fp16 W2
__device__ __align__(16) __half g_hh1[(size_t)NN * F1];   // fp16 (x@W1)*dinv
__device__ __align__(16) __half g_h1h[(size_t)NN * F1];   // fp16 relu'd layer-1 out
__device__ __align__(16) __half g_hh2[(size_t)NN * F2];   // fp16 (h1@W2)*dinv
__device__ int g_is64;

__device__ __forceinline__ uint32_t smem_u32(const void* p) {
    uint32_t a;
    asm("{ .reg .u64 t; cvta.to.shared.u64 t, %1; cvt.u32.u64 %0, t; }" : "=r"(a) : "l"(p));
    return a;
}

#define MMA16816(d, a0, a1, a2, a3, b0, b1)                                   \
    asm volatile(                                                             \
        "mma.sync.aligned.m16n8k16.row.col.f32.f16.f16.f32 "                  \
        "{%0,%1,%2,%3}, {%4,%5,%6,%7}, {%8,%9}, {%0,%1,%2,%3};"               \
        : "+f"((d)[0]), "+f"((d)[1]), "+f"((d)[2]), "+f"((d)[3])              \
        : "r"(a0), "r"(a1), "r"(a2), "r"(a3), "r"(b0), "r"(b1))

#define LDSM_X4(r0, r1, r2, r3, addr)                                         \
    asm volatile("ldmatrix.sync.aligned.m8n8.x4.shared.b16 {%0,%1,%2,%3}, [%4];" \
        : "=r"(r0), "=r"(r1), "=r"(r2), "=r"(r3) : "r"(addr))

#define LDSM_X4_T(r0, r1, r2, r3, addr)                                       \
    asm volatile("ldmatrix.sync.aligned.m8n8.x4.trans.shared.b16 {%0,%1,%2,%3}, [%4];" \
        : "=r"(r0), "=r"(r1), "=r"(r2), "=r"(r3) : "r"(addr))

// -------- edge dtype detection (int64 vs int32) --------
__global__ void k_detect(const int* __restrict__ w, int nwords) {
    __shared__ int ok;
    if (threadIdx.x == 0) ok = 1;
    __syncthreads();
    for (int i = threadIdx.x; i < nwords / 2; i += blockDim.x)
        if (w[2 * i + 1] != 0) ok = 0;   // benign race
    __syncthreads();
    if (threadIdx.x == 0) g_is64 = ok;
}
__device__ __forceinline__ int edge_at(const void* p, int i, int is64) {
    if (is64) return (int)((const long long*)p)[i];
    return ((const int*)p)[i];
}

__global__ void k_zeroint(int* __restrict__ p, int n) {
    int i = blockIdx.x * blockDim.x + threadIdx.x;
    if (i < n) p[i] = 0;
}
__global__ void k_edgedeg(const void* __restrict__ ei, int* __restrict__ deg, int E) {
    int i = blockIdx.x * blockDim.x + threadIdx.x;
    if (i >= E) return;
    int d = edge_at(ei, E + i, g_is64);
    atomicAdd(deg + d, 1);
}

// -------- fp32 -> fp16 bulk convert --------
__global__ void k_f2h(const float4* __restrict__ src, uint2* __restrict__ dst, int n4) {
    int i = blockIdx.x * blockDim.x + threadIdx.x;
    if (i >= n4) return;
    float4 v = src[i];
    __half2 h0 = __floats2half2_rn(v.x, v.y);
    __half2 h1 = __floats2half2_rn(v.z, v.w);
    uint2 o;
    o.x = *(uint32_t*)&h0;
    o.y = *(uint32_t*)&h1;
    dst[i] = o;
}

// -------- 3-phase parallel exclusive scan --------
__global__ __launch_bounds__(SCAN_B) void k_scan1(
    const int* __restrict__ deg, int* __restrict__ off, int* __restrict__ bsum)
{
    __shared__ int sh[SCAN_B];
    int t = threadIdx.x;
    int idx = blockIdx.x * SCAN_B + t;
    int v = (idx < NN) ? deg[idx] : 0;
    sh[t] = v;
    __syncthreads();
#pragma unroll
    for (int d = 1; d < SCAN_B; d <<= 1) {
        int u = 0;
        if (t >= d) u = sh[t - d];
        __syncthreads();
        if (t >= d) sh[t] += u;
        __syncthreads();
    }
    if (idx < NN) off[idx] = sh[t] - v;
    if (t == SCAN_B - 1) bsum[blockIdx.x] = sh[t];
}
__global__ void k_scan2(int* __restrict__ bsum, int* __restrict__ off_last) {
    __shared__ int sh[64];
    int t = threadIdx.x;
    int v = (t < NBLK) ? bsum[t] : 0;
    sh[t] = v;
    __syncthreads();
#pragma unroll
    for (int d = 1; d < 64; d <<= 1) {
        int u = 0;
        if (t >= d) u = sh[t - d];
        __syncthreads();
        if (t >= d) sh[t] += u;
        __syncthreads();
    }
    if (t < NBLK) bsum[t] = sh[t] - v;
    if (t == 63) *off_last = sh[63];
}
__global__ void k_scan3(int* __restrict__ off, int* __restrict__ cur,
                        const int* __restrict__ bsum, const int* __restrict__ deg,
                        float* __restrict__ dinv)
{
    int idx = blockIdx.x * SCAN_B + threadIdx.x;
    if (idx >= NN) return;
    int o = off[idx] + bsum[blockIdx.x];
    off[idx] = o;
    cur[idx] = o;
    dinv[idx] = rsqrtf((float)deg[idx] + 1.0f);
}

__global__ void k_bucket(const void* __restrict__ ei, int* __restrict__ cur,
                         int* __restrict__ srcs, int E) {
    int i = blockIdx.x * blockDim.x + threadIdx.x;
    if (i >= E) return;
    int is64 = g_is64;
    int s = edge_at(ei, i, is64);
    int d = edge_at(ei, E + i, is64);
    int p = atomicAdd(cur + d, 1);
    srcs[p] = s;
}

// ======== fp16 HMMA GEMM: Ch = half((Ah@Bh) * dinv[row]),  K=256 ========
// Ah: [M,256] fp16 row-major, Bh: [256,N] fp16 row-major.
// CTA 128x128, 8 warps (warp tile 64x32), BK=32, double-buffered smem,
// ldmatrix frags (A non-trans from [m][k]; B trans from natural [k][n]).
__global__ __launch_bounds__(256) void k_gemm_h(
    const __half* __restrict__ Ah, const __half* __restrict__ Bh,
    const float* __restrict__ dinv, __half* __restrict__ Ch, int M, int N)
{
    constexpr int K = 256;
    constexpr int LDA = 40;                 // halfs: 32 + 8 pad (80B stride)
    constexpr int LDB = 136;                // halfs: 128 + 8 pad (272B stride)
    __shared__ __half As[2][128][LDA];
    __shared__ __half Bs[2][32][LDB];

    int tid = threadIdx.x;
    int w = tid >> 5;
    int lane = tid & 31;
    int gid = lane >> 2;
    int tig = lane & 3;
    int warp_m = w >> 2;                    // 0..1
    int warp_n = w & 3;                     // 0..3
    int row0 = blockIdx.y * 128;
    int col0 = blockIdx.x * 128;

    uint32_t asb = smem_u32(&As[0][0][0]);
    uint32_t bsb = smem_u32(&Bs[0][0][0]);

    float acc[4][4][4];
#pragma unroll
    for (int mt = 0; mt < 4; mt++)
#pragma unroll
        for (int nt = 0; nt < 4; nt++)
#pragma unroll
            for (int q = 0; q < 4; q++) acc[mt][nt][q] = 0.f;

    uint4 ra[2], rb[2];

    auto ldregs = [&](int kt) {
#pragma unroll
        for (int i = 0; i < 2; i++) {
            int u = tid + (i << 8);
            int r = u >> 2, c = (u & 3) * 8;          // A: 4x16B per row of 32 halfs
            int grow = row0 + r;
            ra[i] = (grow < M) ? *(const uint4*)(Ah + (size_t)grow * K + kt + c)
                               : make_uint4(0u, 0u, 0u, 0u);
            int k = u >> 4, cb = (u & 15) * 8;        // B: 16x16B per row of 128 halfs
            rb[i] = *(const uint4*)(Bh + (size_t)(kt + k) * N + col0 + cb);
        }
    };
    auto sts = [&](int b) {
#pragma unroll
        for (int i = 0; i < 2; i++) {
            int u = tid + (i << 8);
            *(uint4*)&As[b][u >> 2][(u & 3) * 8] = ra[i];
            *(uint4*)&Bs[b][u >> 4][(u & 15) * 8] = rb[i];
        }
    };
    auto mmabuf = [&](int b) {
#pragma unroll
        for (int k2 = 0; k2 < 32; k2 += 16) {
            uint32_t bf[4][2];
#pragma unroll
            for (int np = 0; np < 2; np++) {
                int brow = k2 + ((lane >> 3) & 1) * 8 + (lane & 7);
                int bcol = warp_n * 32 + np * 16 + (lane >> 4) * 8;
                uint32_t ad = bsb + (uint32_t)(((b << 5) + brow) * LDB + bcol) * 2;
                LDSM_X4_T(bf[np * 2][0], bf[np * 2][1], bf[np * 2 + 1][0], bf[np * 2 + 1][1], ad);
            }
#pragma unroll
            for (int mt = 0; mt < 4; mt++) {
                int arow = warp_m * 64 + mt * 16 + (lane & 15);
                int kc = k2 + (lane >> 4) * 8;
                uint32_t ad = asb + (uint32_t)(((b << 7) + arow) * LDA + kc) * 2;
                uint32_t a0, a1, a2, a3;
                LDSM_X4(a0, a1, a2, a3, ad);
#pragma unroll
                for (int nt = 0; nt < 4; nt++)
                    MMA16816(acc[mt][nt], a0, a1, a2, a3, bf[nt][0], bf[nt][1]);
            }
        }
    };

    ldregs(0);
    sts(0);
    __syncthreads();
#pragma unroll
    for (int ch = 0; ch < K / 32; ch++) {
        if (ch < K / 32 - 1) ldregs((ch + 1) * 32);   // prefetch next chunk
        mmabuf(ch & 1);
        if (ch < K / 32 - 1) sts((ch + 1) & 1);
        __syncthreads();
    }

    // epilogue: scale by dinv, store fp16
#pragma unroll
    for (int mt = 0; mt < 4; mt++) {
        int r0 = row0 + warp_m * 64 + mt * 16 + gid;
        int r1 = r0 + 8;
        float s0 = (r0 < M) ? dinv[r0] : 0.f;
        float s1 = (r1 < M) ? dinv[r1] : 0.f;
#pragma unroll
        for (int nt = 0; nt < 4; nt++) {
            int c = col0 + warp_n * 32 + nt * 8 + tig * 2;
            if (r0 < M) {
                __half2 h = __floats2half2_rn(acc[mt][nt][0] * s0, acc[mt][nt][1] * s0);
                *(__half2*)(Ch + (size_t)r0 * N + c) = h;
            }
            if (r1 < M) {
                __half2 h = __floats2half2_rn(acc[mt][nt][2] * s1, acc[mt][nt][3] * s1);
                *(__half2*)(Ch + (size_t)r1 * N + c) = h;
            }
        }
    }
}

// -------- CSR gather-reduce over fp16 features, fp32 accumulate --------
// OUTH: write fp16 (for layer-1 output feeding GEMM2); else fp32.
template <int FH, bool RELU, bool OUTH>
__global__ __launch_bounds__(256) void k_gather_h(
    const int* __restrict__ off, const int* __restrict__ srcs,
    const __half* __restrict__ hsh, const float* __restrict__ dinv,
    const float* __restrict__ bias, void* __restrict__ outv)
{
    constexpr int F = 32 * FH;
    int node = (blockIdx.x * blockDim.x + threadIdx.x) >> 5;
    int lane = threadIdx.x & 31;
    if (node >= NN) return;
    const __half* base = hsh + lane * FH;

    float acc[FH];
#pragma unroll
    for (int j = 0; j < FH; j++) acc[j] = 0.f;

    auto accum = [&](int s) {
        const __half* p = base + (size_t)s * F;
        if (FH == 8) {
            uint4 v = *(const uint4*)p;
            float2 f;
            f = __half22float2(*(__half2*)&v.x); acc[0] += f.x; acc[1] += f.y;
            f = __half22float2(*(__half2*)&v.y); acc[2] += f.x; acc[3] += f.y;
            f = __half22float2(*(__half2*)&v.z); acc[4] += f.x; acc[5] += f.y;
            f = __half22float2(*(__half2*)&v.w); acc[6] += f.x; acc[7] += f.y;
        } else {
            uint2 v = *(const uint2*)p;
            float2 f;
            f = __half22float2(*(__half2*)&v.x); acc[0] += f.x; acc[1] += f.y;
            f = __half22float2(*(__half2*)&v.y); acc[2] += f.x; acc[3] += f.y;
        }
    };

    accum(node);                                   // self loop
    int e = off[node], end = off[node + 1];
    for (; e + 4 <= end; e += 4) {
        int s0 = srcs[e], s1 = srcs[e + 1], s2 = srcs[e + 2], s3 = srcs[e + 3];
        accum(s0); accum(s1); accum(s2); accum(s3);
    }
    for (; e < end; e++) accum(srcs[e]);

    float sc = dinv[node];
    const float* bp = bias + lane * FH;
    float o[FH];
#pragma unroll
    for (int j = 0; j < FH; j += 4) {
        float4 b = *(const float4*)(bp + j);
        o[j + 0] = sc * acc[j + 0] + b.x;
        o[j + 1] = sc * acc[j + 1] + b.y;
        o[j + 2] = sc * acc[j + 2] + b.z;
        o[j + 3] = sc * acc[j + 3] + b.w;
        if (RELU) {
            o[j + 0] = fmaxf(o[j + 0], 0.f); o[j + 1] = fmaxf(o[j + 1], 0.f);
            o[j + 2] = fmaxf(o[j + 2], 0.f); o[j + 3] = fmaxf(o[j + 3], 0.f);
        }
    }
    if (OUTH) {
        __half* dst = (__half*)outv + (size_t)node * F + lane * FH;
#pragma unroll
        for (int j = 0; j < FH; j += 4) {
            __half2 h0 = __floats2half2_rn(o[j + 0], o[j + 1]);
            __half2 h1 = __floats2half2_rn(o[j + 2], o[j + 3]);
            uint2 hp;
            hp.x = *(uint32_t*)&h0;
            hp.y = *(uint32_t*)&h1;
            *(uint2*)(dst + j) = hp;
        }
    } else {
        float* dst = (float*)outv + (size_t)node * F + lane * FH;
#pragma unroll
        for (int j = 0; j < FH; j += 4) {
            float4 v = make_float4(o[j + 0], o[j + 1], o[j + 2], o[j + 3]);
            *(float4*)(dst + j) = v;
        }
    }
}

extern "C" void kernel_launch(void* const* d_in, const int* in_sizes, int n_in,
                              void* d_out, int out_size)
{
    const float* x  = (const float*)d_in[0];
    const void*  ei = d_in[1];
    const float* W1 = (const float*)d_in[2];
    const float* b1 = (const float*)d_in[3];
    const float* W2 = (const float*)d_in[4];
    const float* b2 = (const float*)d_in[5];
    const int E = in_sizes[1] / 2;
    const int n = NN;

    int *deg, *off, *cur, *srcs, *bsum;
    float *dinv;
    __half *hx, *hw1, *hw2, *hh1, *h1h, *hh2;
    cudaGetSymbolAddress((void**)&deg,  g_deg);
    cudaGetSymbolAddress((void**)&off,  g_off);
    cudaGetSymbolAddress((void**)&cur,  g_cur);
    cudaGetSymbolAddress((void**)&srcs, g_srcs);
    cudaGetSymbolAddress((void**)&bsum, g_bsum);
    cudaGetSymbolAddress((void**)&dinv, g_dinv);
    cudaGetSymbolAddress((void**)&hx,   g_hx);
    cudaGetSymbolAddress((void**)&hw1,  g_hw1);
    cudaGetSymbolAddress((void**)&hw2,  g_hw2);
    cudaGetSymbolAddress((void**)&hh1,  g_hh1);
    cudaGetSymbolAddress((void**)&h1h,  g_h1h);
    cudaGetSymbolAddress((void**)&hh2,  g_hh2);

    // dtype sniff
    k_detect<<<1, 256>>>((const int*)ei, 8192);

    // fp16 pre-conversion of x, W1, W2
    {
        int n4 = n * F1 / 4;
        k_f2h<<<(n4 + 255) / 256, 256>>>((const float4*)x, (uint2*)hx, n4);
        k_f2h<<<(256 * F1 / 4 + 255) / 256, 256>>>((const float4*)W1, (uint2*)hw1, 256 * F1 / 4);
        k_f2h<<<(256 * F2 / 4 + 255) / 256, 256>>>((const float4*)W2, (uint2*)hw2, 256 * F2 / 4);
    }

    // degree -> parallel scan -> dinv -> CSR buckets
    k_zeroint<<<(n + 255) / 256, 256>>>(deg, n);
    k_edgedeg<<<(E + 255) / 256, 256>>>(ei, deg, E);
    k_scan1<<<NBLK, SCAN_B>>>(deg, off, bsum);
    k_scan2<<<1, 64>>>(bsum, off + NN);
    k_scan3<<<NBLK, SCAN_B>>>(off, cur, bsum, deg, dinv);
    k_bucket<<<(E + 255) / 256, 256>>>(ei, cur, srcs, E);

    const int MT = (n + 127) / 128;   // 391 row tiles

    // ---- layer 1 ----
    {
        dim3 grid(F1 / 128, MT);
        k_gemm_h<<<grid, 256>>>(hx, hw1, dinv, hh1, n, F1);
    }
    k_gather_h<8, true, true><<<(n * 32 + 255) / 256, 256>>>(off, srcs, hh1, dinv, b1, h1h);

    // ---- layer 2 ----
    {
        dim3 grid(F2 / 128, MT);
        k_gemm_h<<<grid, 256>>>(h1h, hw2, dinv, hh2, n, F2);
    }
    k_gather_h<4, false, false><<<(n * 32 + 255) / 256, 256>>>(off, srcs, hh2, dinv, b2, d_out);
}